// round 16
// baseline (speedup 1.0000x reference)
#include <cuda_runtime.h>
#include <cuda_fp16.h>
#include <cuda_bf16.h>
#include <math.h>
#include <stdint.h>

// Problem constants
#define BT   4096      // B*S tokens
#define DD   1024
#define HH   2048
#define OO   1024
#define EE   8
#define TOPK 2
#define NPAIR (BT*TOPK)    // 8192
#define OUT_TENSOR (BT*OO) // 4194304

// ================= small helpers =================
__device__ __forceinline__ uint32_t smem_to_u32(const void* p) {
    uint32_t a;
    asm("{ .reg .u64 t; cvta.to.shared.u64 t, %1; cvt.u32.u64 %0, t; }" : "=r"(a) : "l"(p));
    return a;
}
#define CP_ASYNC16(dst, src) \
    asm volatile("cp.async.ca.shared.global [%0], [%1], 16;" :: "r"(dst), "l"(src))
#define CP_ASYNC16_CG(dst, src) \
    asm volatile("cp.async.cg.shared.global [%0], [%1], 16;" :: "r"(dst), "l"(src))
#define CP_COMMIT() asm volatile("cp.async.commit_group;" ::: "memory")
#define CP_WAIT1()  asm volatile("cp.async.wait_group 1;" ::: "memory")
#define CP_WAIT0()  asm volatile("cp.async.wait_group 0;" ::: "memory")

__device__ __forceinline__ void ldsm_x4(uint32_t& r0, uint32_t& r1, uint32_t& r2, uint32_t& r3,
                                        uint32_t addr) {
    asm volatile("ldmatrix.sync.aligned.m8n8.x4.shared.b16 {%0,%1,%2,%3}, [%4];"
                 : "=r"(r0), "=r"(r1), "=r"(r2), "=r"(r3) : "r"(addr));
}
__device__ __forceinline__ void ldsm_x4_t(uint32_t& r0, uint32_t& r1, uint32_t& r2, uint32_t& r3,
                                          uint32_t addr) {
    asm volatile("ldmatrix.sync.aligned.m8n8.x4.trans.shared.b16 {%0,%1,%2,%3}, [%4];"
                 : "=r"(r0), "=r"(r1), "=r"(r2), "=r"(r3) : "r"(addr));
}
__device__ __forceinline__ void mma_f16(float& c0, float& c1, float& c2, float& c3,
                                        uint32_t a0, uint32_t a1, uint32_t a2, uint32_t a3,
                                        uint32_t b0, uint32_t b1) {
    asm volatile(
        "mma.sync.aligned.m16n8k16.row.col.f32.f16.f16.f32 "
        "{%0,%1,%2,%3}, {%4,%5,%6,%7}, {%8,%9}, {%0,%1,%2,%3};"
        : "+f"(c0), "+f"(c1), "+f"(c2), "+f"(c3)
        : "r"(a0), "r"(a1), "r"(a2), "r"(a3), "r"(b0), "r"(b1));
}

// ================= scratch =================
__device__ __half d_h1[(size_t)NPAIR * HH];          // 32 MB
__device__ __half d_h2[(size_t)NPAIR * HH];          // 32 MB
__device__ __half d_xh[(size_t)BT * DD];             // 8 MB (fp16 x)
__device__ __half d_w1h[(size_t)EE * DD * HH];       // 32 MB  [E][D][H] (K x N row-major)
__device__ __half d_w2h[(size_t)EE * HH * HH];       // 64 MB
__device__ __half d_w3h[(size_t)EE * HH * OO];       // 32 MB
__device__ float  d_y[(size_t)NPAIR * OO];           // 32 MB gated partial outputs by position
__device__ int   d_pair_token[NPAIR];
__device__ float d_pair_gate[NPAIR];
__device__ int   d_pair_pos[NPAIR];                  // pair j -> position
__device__ int   d_counts[EE];
__device__ int   d_offsets[EE];
__device__ int   d_cursor[EE];
__device__ float d_sum_probs[EE];
__device__ float d_sum_gates[EE];
__device__ int   d_top_idx[NPAIR];
__device__ float d_top_g[NPAIR];
// cross-phase sync counters (mega kernel)
__device__ int   d_done1[EE * 32];
__device__ int   d_done2[EE * 32];
__device__ int   d_conv2done;
__device__ int   d_conv3done;

#define N1 ((size_t)EE * DD * HH)   // 16,777,216
#define N2 ((size_t)EE * HH * HH)   // 33,554,432
#define N3 ((size_t)EE * HH * OO)   // 16,777,216
#define NCONV2B 16384               // N2 / 2048
#define NCONV3B 8192                // N3 / 2048

// ---- shared fp32->fp16 convert of 8 contiguous elements ----
__device__ __forceinline__ void conv8(const float* __restrict__ src,
                                      __half* __restrict__ dst, size_t off) {
    float4 f0 = *(const float4*)(src + off);
    float4 f1 = *(const float4*)(src + off + 4);
    __half2 h[4];
    h[0] = __floats2half2_rn(f0.x, f0.y);
    h[1] = __floats2half2_rn(f0.z, f0.w);
    h[2] = __floats2half2_rn(f1.x, f1.y);
    h[3] = __floats2half2_rn(f1.z, f1.w);
    *(uint4*)(dst + off) = *(uint4*)h;
}

// ================= fat pre: W1 convert + gating (emits fp16 x) ==============
#define NCONV1B 8192u    // N1 / (256*8)
__global__ __launch_bounds__(256)
void fatpre_kernel(const float* __restrict__ W1,
                   const float* __restrict__ x,
                   const float* __restrict__ Wg,
                   const float* __restrict__ bg) {
    if (blockIdx.x < NCONV1B) {
        size_t i8 = ((size_t)blockIdx.x * 256 + threadIdx.x) * 8;
        conv8(W1, d_w1h, i8);
        return;
    }
    int t = blockIdx.x - NCONV1B;
    int tid = threadIdx.x;
    float acc[EE];
#pragma unroll
    for (int e = 0; e < EE; e++) acc[e] = 0.0f;
    const float* xr = x + (size_t)t * DD;
    __half* xh = d_xh + (size_t)t * DD;
    for (int d = tid; d < DD; d += 256) {
        float xv = xr[d];
        xh[d] = __float2half(xv);
        const float* w = Wg + (size_t)d * EE;
#pragma unroll
        for (int e = 0; e < EE; e++) acc[e] += xv * w[e];
    }
#pragma unroll
    for (int e = 0; e < EE; e++) {
#pragma unroll
        for (int off = 16; off > 0; off >>= 1)
            acc[e] += __shfl_down_sync(0xffffffffu, acc[e], off);
    }
    __shared__ float sred[8][EE];
    int warp = tid >> 5, lane = tid & 31;
    if (lane == 0) {
#pragma unroll
        for (int e = 0; e < EE; e++) sred[warp][e] = acc[e];
    }
    __syncthreads();
    if (tid == 0) {
        float logit[EE];
#pragma unroll
        for (int e = 0; e < EE; e++) {
            float s = sred[0][e];
#pragma unroll
            for (int w = 1; w < 8; w++) s += sred[w][e];
            logit[e] = s + bg[e];
        }
        float m = logit[0];
#pragma unroll
        for (int e = 1; e < EE; e++) m = fmaxf(m, logit[e]);
        float p[EE], se = 0.0f;
#pragma unroll
        for (int e = 0; e < EE; e++) { p[e] = __expf(logit[e] - m); se += p[e]; }
        float inv = 1.0f / se;
#pragma unroll
        for (int e = 0; e < EE; e++) atomicAdd(&d_sum_probs[e], p[e] * inv);
        int i0 = 0;
#pragma unroll
        for (int e = 1; e < EE; e++) if (logit[e] > logit[i0]) i0 = e;
        int i1 = (i0 == 0) ? 1 : 0;
#pragma unroll
        for (int e = 0; e < EE; e++)
            if (e != i0 && logit[e] > logit[i1]) i1 = e;
        float l0 = logit[i0], l1 = logit[i1];
        float mm = fmaxf(l0, l1);
        float e0 = __expf(l0 - mm), e1 = __expf(l1 - mm);
        float s2 = e0 + e1;
        float g0 = e0 / s2, g1 = e1 / s2;
        atomicAdd(&d_sum_gates[i0], g0);
        atomicAdd(&d_sum_gates[i1], g1);
        atomicAdd(&d_counts[i0], 1);
        atomicAdd(&d_counts[i1], 1);
        d_top_idx[t * 2 + 0] = i0;  d_top_g[t * 2 + 0] = g0;
        d_top_idx[t * 2 + 1] = i1;  d_top_g[t * 2 + 1] = g1;
    }
}

// tiny init for accumulators + sync counters (before gating)
__global__ void init_acc_kernel() {
    int tid = threadIdx.x;   // 512
    if (tid < EE) {
        d_counts[tid] = 0;
        d_sum_probs[tid] = 0.0f;
        d_sum_gates[tid] = 0.0f;
    }
    if (tid < EE * 32) { d_done1[tid] = 0; d_done2[tid] = 0; }
    if (tid == 0) { d_conv2done = 0; d_conv3done = 0; }
}

// ================= finalize: offsets + aux stats + tail-zero =================
__global__ void finalize_kernel(float* __restrict__ out, int out_size) {
    if (threadIdx.x == 0 && blockIdx.x == 0) {
        int off = 0;
        for (int e = 0; e < EE; e++) {
            d_offsets[e] = off;
            off += d_counts[e];
            d_cursor[e] = 0;
        }
        for (int i = OUT_TENSOR; i < out_size; i++) out[i] = 0.0f;  // tail is tiny
        float lb = 0.0f, ent = 0.0f;
        const float invT = 1.0f / (float)BT;
        for (int e = 0; e < EE; e++) {
            float ap = d_sum_probs[e] * invT;
            float ac = d_sum_gates[e] * invT;
            lb += ap * ac;
            ent -= ap * logf(ap + 1e-8f);
            out[OUT_TENSOR + 1 + e] = ac;
        }
        out[OUT_TENSOR] = 0.01f * (float)EE * lb;
        out[OUT_TENSOR + 1 + EE] = ent;
    }
}

// ================= scatter =================
__global__ void scatter_kernel() {
    int j = blockIdx.x * blockDim.x + threadIdx.x;
    if (j >= NPAIR) return;
    int t = j >> 1;
    int e = d_top_idx[j];
    int pos = d_offsets[e] + atomicAdd(&d_cursor[e], 1);
    d_pair_token[pos] = t;
    d_pair_gate[pos]  = d_top_g[j];
    d_pair_pos[j] = pos;
}

// ================= fp16 mma.sync expert GEMM body (device fn) =================
#define KC 64
#define STAGE_BYTES 32768            // A 16KB + B 16KB
#define HDR_BYTES 1024
#define NSTAGE 3
#define SMEM_DYN (HDR_BYTES + NSTAGE*STAGE_BYTES)

__device__ __forceinline__ void spin_ge(int* ctr, int target) {
    while (atomicAdd(ctr, 0) < target) __nanosleep(64);
}

template<int LAYER>
__device__ __forceinline__ void gemm_body(int e, int mtile, int nblk,
                                          const float* __restrict__ bias) {
    constexpr int Kd = (LAYER == 1) ? DD : HH;
    constexpr int Nd = (LAYER == 3) ? OO : HH;
    constexpr int NCH = Kd / KC;   // 16 or 32

    const int cnt = d_counts[e];
    if (mtile * 128 >= cnt) return;
    const int base = d_offsets[e];

    extern __shared__ char smem_raw[];
    const uint32_t sb = smem_to_u32(smem_raw);
    int* stok    = (int*)smem_raw;            // [128]
    float* sgate = (float*)(smem_raw + 512);  // [128]

    const int tid = threadIdx.x;
    const int wid = tid >> 5;
    const int lid = tid & 31;
    const int g   = lid >> 2;     // 0..7
    const int tg  = lid & 3;      // 0..3
    const int m0  = (wid & 1) * 64;
    const int n0  = (wid >> 1) * 32;

    // ---- dependency spin (producers have strictly smaller bids) ----
    if (tid == 0) {
        if (LAYER == 2) {
            spin_ge(&d_conv2done, NCONV2B);
            spin_ge(&d_done1[e * 32 + mtile], 16);
        } else if (LAYER == 3) {
            spin_ge(&d_conv3done, NCONV3B);
            spin_ge(&d_done2[e * 32 + mtile], 16);
        }
    }
    if (tid < 128) {
        int gr = mtile * 128 + tid;
        int idx = base + min(gr, cnt - 1);
        stok[tid]  = d_pair_token[idx];
        sgate[tid] = d_pair_gate[idx];
    }
    __syncthreads();

    // ---- cp.async mappings ----
    const int lsubA = tid & 7, lrowA = tid >> 3;     // A: 128 rows x 128B
    const int lsubB = tid & 15, lrowB = tid >> 4;    // B: 64 rows x 256B

    const __half* Wh = (LAYER == 1) ? d_w1h : ((LAYER == 2) ? d_w2h : d_w3h);
    const __half* WhE = Wh + (size_t)e * Kd * Nd + (size_t)(nblk * 128);
    const __half* hsrc = (LAYER == 2) ? d_h1 : d_h2;

    uint32_t dstoffA[4], dstoffB[4];
    const char* asrc[4];
    const char* bsrc[4];
#pragma unroll
    for (int i = 0; i < 4; i++) {
        int rA = lrowA + 32 * i;
        dstoffA[i] = (uint32_t)(rA * 128 + ((lsubA ^ (rA & 7)) << 4));
        if (LAYER == 1) {
            asrc[i] = (const char*)(d_xh + (size_t)stok[rA] * DD) + lsubA * 16;
        } else {
            int gr = min(mtile * 128 + rA, cnt - 1);
            asrc[i] = (const char*)(hsrc + (size_t)(base + gr) * Kd) + lsubA * 16;
        }
        int rB = lrowB + 16 * i;
        dstoffB[i] = (uint32_t)(rB * 256 + ((lsubB ^ (rB & 7)) << 4));
        bsrc[i] = (const char*)(WhE + (size_t)rB * Nd) + lsubB * 16;
    }
    const size_t bstep = (size_t)KC * Nd * sizeof(__half);  // per-stage B advance

    // ---- ldmatrix lane constants ----
    const int til = lid >> 3, rin = lid & 7;
    const int thi = til >> 1, tlo = til & 1;
    uint32_t rowbaseA[4];
#pragma unroll
    for (int mt = 0; mt < 4; mt++)
        rowbaseA[mt] = (uint32_t)((m0 + mt * 16 + rin + tlo * 8) * 128);
    uint32_t koffA[4];
#pragma unroll
    for (int ks = 0; ks < 4; ks++)
        koffA[ks] = (uint32_t)((((ks * 2) + thi) ^ rin) << 4);
    const int klane = rin + tlo * 8;   // 0..15
    uint32_t lbB[2];
#pragma unroll
    for (int pr = 0; pr < 2; pr++) {
        int nc = (n0 >> 3) + pr * 2 + thi;
        lbB[pr] = (uint32_t)(klane * 256 + ((nc ^ (klane & 7)) << 4));
    }

    float acc[4][4][4];
#pragma unroll
    for (int mt = 0; mt < 4; mt++)
#pragma unroll
        for (int nt = 0; nt < 4; nt++)
#pragma unroll
            for (int c = 0; c < 4; c++) acc[mt][nt][c] = 0.0f;

    auto issue = [&](int s) {
        uint32_t sa = sb + HDR_BYTES + (s % NSTAGE) * STAGE_BYTES;
        uint32_t sB = sa + 16384;
        size_t aoff = (size_t)s * 128;       // 64 halves = 128 bytes along K
        size_t boff = (size_t)s * bstep;
        if (LAYER == 1) {
#pragma unroll
            for (int i = 0; i < 4; i++) CP_ASYNC16(sa + dstoffA[i], asrc[i] + aoff);
        } else {
            // .cg: bypass L1 (h1/h2 just produced by other CTAs in this launch)
#pragma unroll
            for (int i = 0; i < 4; i++) CP_ASYNC16_CG(sa + dstoffA[i], asrc[i] + aoff);
        }
#pragma unroll
        for (int i = 0; i < 4; i++) CP_ASYNC16_CG(sB + dstoffB[i], bsrc[i] + boff);
    };

    issue(0); CP_COMMIT();
    issue(1); CP_COMMIT();

    for (int c = 0; c < NCH; c++) {
        if (c + 1 < NCH) { CP_WAIT1(); } else { CP_WAIT0(); }
        __syncthreads();
        if (c + 2 < NCH) { issue(c + 2); CP_COMMIT(); }

        uint32_t sa = sb + HDR_BYTES + (c % NSTAGE) * STAGE_BYTES;
        uint32_t sB = sa + 16384;
#pragma unroll
        for (int ks = 0; ks < 4; ks++) {
            uint32_t b[8];
            ldsm_x4_t(b[0], b[1], b[2], b[3], sB + lbB[0] + ks * 4096);
            ldsm_x4_t(b[4], b[5], b[6], b[7], sB + lbB[1] + ks * 4096);
#pragma unroll
            for (int mt = 0; mt < 4; mt++) {
                uint32_t a0, a1, a2, a3;
                ldsm_x4(a0, a1, a2, a3, sa + rowbaseA[mt] + koffA[ks]);
                mma_f16(acc[mt][0][0], acc[mt][0][1], acc[mt][0][2], acc[mt][0][3],
                        a0, a1, a2, a3, b[0], b[1]);
                mma_f16(acc[mt][1][0], acc[mt][1][1], acc[mt][1][2], acc[mt][1][3],
                        a0, a1, a2, a3, b[2], b[3]);
                mma_f16(acc[mt][2][0], acc[mt][2][1], acc[mt][2][2], acc[mt][2][3],
                        a0, a1, a2, a3, b[4], b[5]);
                mma_f16(acc[mt][3][0], acc[mt][3][1], acc[mt][3][2], acc[mt][3][3],
                        a0, a1, a2, a3, b[6], b[7]);
            }
        }
    }

    // ---- epilogue ----
    const float* biasE = bias + (size_t)e * Nd + nblk * 128;
    __half* hdst = (LAYER == 1) ? d_h1 : d_h2;

#pragma unroll
    for (int mt = 0; mt < 4; mt++) {
#pragma unroll
        for (int nt = 0; nt < 4; nt++) {
            int col = n0 + nt * 8 + tg * 2;
            float bv0 = biasE[col], bv1 = biasE[col + 1];
#pragma unroll
            for (int half = 0; half < 2; half++) {
                int lr = m0 + mt * 16 + g + half * 8;
                int grow = mtile * 128 + lr;
                if (grow >= cnt) continue;
                float v0 = acc[mt][nt][half * 2 + 0] + bv0;
                float v1 = acc[mt][nt][half * 2 + 1] + bv1;
                if (LAYER != 3) {
                    __half2 v = __floats2half2_rn(fmaxf(v0, 0.0f), fmaxf(v1, 0.0f));
                    *(__half2*)(hdst + (size_t)(base + grow) * HH + nblk * 128 + col) = v;
                } else {
                    float gt = sgate[lr];
                    float2 v = make_float2(gt * v0, gt * v1);
                    *(float2*)(d_y + (size_t)(base + grow) * OO + nblk * 128 + col) = v;
                }
            }
        }
    }

    // ---- publish completion ----
    if (LAYER != 3) {
        __syncthreads();
        if (tid == 0) {
            __threadfence();
            atomicAdd((LAYER == 1) ? &d_done1[e * 32 + mtile] : &d_done2[e * 32 + mtile], 1);
        }
    }
}

// ================= mega kernel: gemm1 | convW2 | gemm2 | convW3 | gemm3 ========
// grid (16, 32, 72); z ranges select phase. Producers have smaller bids than
// consumers, so spin-waits cannot deadlock.
__global__ __launch_bounds__(256, 2)
void mega_kernel(const float* __restrict__ b1,
                 const float* __restrict__ b2,
                 const float* __restrict__ b3,
                 const float* __restrict__ W2,
                 const float* __restrict__ W3) {
    const int z = blockIdx.z;
    if (z < 8) {
        gemm_body<1>(z, blockIdx.y, blockIdx.x, b1);
    } else if (z < 40) {
        // convert W2: 16384 blocks
        size_t cb = (size_t)(z - 8) * 512 + blockIdx.y * 16 + blockIdx.x;
        conv8(W2, d_w2h, (cb * 256 + threadIdx.x) * 8);
        __syncthreads();
        if (threadIdx.x == 0) { __threadfence(); atomicAdd(&d_conv2done, 1); }
    } else if (z < 48) {
        gemm_body<2>(z - 40, blockIdx.y, blockIdx.x, b2);
    } else if (z < 64) {
        // convert W3: 8192 blocks
        size_t cb = (size_t)(z - 48) * 512 + blockIdx.y * 16 + blockIdx.x;
        conv8(W3, d_w3h, (cb * 256 + threadIdx.x) * 8);
        __syncthreads();
        if (threadIdx.x == 0) { __threadfence(); atomicAdd(&d_conv3done, 1); }
    } else {
        if (blockIdx.x >= 8) return;   // gemm3 has only 8 n-blocks
        gemm_body<3>(z - 64, blockIdx.y, blockIdx.x, b3);
    }
}

// ================= combine: out[t] = y[pos(2t)] + y[pos(2t+1)] =================
__global__ void combine_kernel(float* __restrict__ out) {
    int t = blockIdx.x;
    int p0 = d_pair_pos[2 * t];
    int p1 = d_pair_pos[2 * t + 1];
    const float4* y0 = (const float4*)(d_y + (size_t)p0 * OO);
    const float4* y1 = (const float4*)(d_y + (size_t)p1 * OO);
    float4* dst = (float4*)(out + (size_t)t * OO);
    int i = threadIdx.x;             // 256 threads, 256 float4 per row
    float4 a = y0[i], b = y1[i];
    dst[i] = make_float4(a.x + b.x, a.y + b.y, a.z + b.z, a.w + b.w);
}

// ================= launch =================
extern "C" void kernel_launch(void* const* d_in, const int* in_sizes, int n_in,
                              void* d_out, int out_size) {
    const float* x  = (const float*)d_in[0];
    const float* Wg = (const float*)d_in[1];
    const float* bg = (const float*)d_in[2];
    const float* W1 = (const float*)d_in[3];
    const float* b1 = (const float*)d_in[4];
    const float* W2 = (const float*)d_in[5];
    const float* b2 = (const float*)d_in[6];
    const float* W3 = (const float*)d_in[7];
    const float* b3 = (const float*)d_in[8];
    float* out = (float*)d_out;

    cudaFuncSetAttribute(mega_kernel, cudaFuncAttributeMaxDynamicSharedMemorySize, SMEM_DYN);

    init_acc_kernel<<<1, 512>>>();                                          // 1
    fatpre_kernel<<<NCONV1B + BT, 256>>>(W1, x, Wg, bg);                    // 2 (W1 conv + gating)
    finalize_kernel<<<1, 32>>>(out, out_size);                              // 3
    scatter_kernel<<<NPAIR / 256, 256>>>();                                 // 4
    mega_kernel<<<dim3(16, 32, 72), 256, SMEM_DYN>>>(b1, b2, b3, W2, W3);   // 5
    combine_kernel<<<BT, 256>>>(out);                                       // 6
}

// round 17
// speedup vs baseline: 1.0825x; 1.0825x over previous
#include <cuda_runtime.h>
#include <cuda_fp16.h>
#include <cuda_bf16.h>
#include <math.h>
#include <stdint.h>

// Problem constants
#define BT   4096      // B*S tokens
#define DD   1024
#define HH   2048
#define OO   1024
#define EE   8
#define TOPK 2
#define NPAIR (BT*TOPK)    // 8192
#define OUT_TENSOR (BT*OO) // 4194304

// ================= small helpers =================
__device__ __forceinline__ uint32_t smem_to_u32(const void* p) {
    uint32_t a;
    asm("{ .reg .u64 t; cvta.to.shared.u64 t, %1; cvt.u32.u64 %0, t; }" : "=r"(a) : "l"(p));
    return a;
}
#define CP_ASYNC16(dst, src) \
    asm volatile("cp.async.ca.shared.global [%0], [%1], 16;" :: "r"(dst), "l"(src))
#define CP_ASYNC16_CG(dst, src) \
    asm volatile("cp.async.cg.shared.global [%0], [%1], 16;" :: "r"(dst), "l"(src))
#define CP_COMMIT() asm volatile("cp.async.commit_group;" ::: "memory")
#define CP_WAIT1()  asm volatile("cp.async.wait_group 1;" ::: "memory")
#define CP_WAIT0()  asm volatile("cp.async.wait_group 0;" ::: "memory")

__device__ __forceinline__ void ldsm_x4(uint32_t& r0, uint32_t& r1, uint32_t& r2, uint32_t& r3,
                                        uint32_t addr) {
    asm volatile("ldmatrix.sync.aligned.m8n8.x4.shared.b16 {%0,%1,%2,%3}, [%4];"
                 : "=r"(r0), "=r"(r1), "=r"(r2), "=r"(r3) : "r"(addr));
}
__device__ __forceinline__ void ldsm_x4_t(uint32_t& r0, uint32_t& r1, uint32_t& r2, uint32_t& r3,
                                          uint32_t addr) {
    asm volatile("ldmatrix.sync.aligned.m8n8.x4.trans.shared.b16 {%0,%1,%2,%3}, [%4];"
                 : "=r"(r0), "=r"(r1), "=r"(r2), "=r"(r3) : "r"(addr));
}
__device__ __forceinline__ void mma_f16(float& c0, float& c1, float& c2, float& c3,
                                        uint32_t a0, uint32_t a1, uint32_t a2, uint32_t a3,
                                        uint32_t b0, uint32_t b1) {
    asm volatile(
        "mma.sync.aligned.m16n8k16.row.col.f32.f16.f16.f32 "
        "{%0,%1,%2,%3}, {%4,%5,%6,%7}, {%8,%9}, {%0,%1,%2,%3};"
        : "+f"(c0), "+f"(c1), "+f"(c2), "+f"(c3)
        : "r"(a0), "r"(a1), "r"(a2), "r"(a3), "r"(b0), "r"(b1));
}

// ================= scratch =================
__device__ __half d_h1[(size_t)NPAIR * HH];          // 32 MB
__device__ __half d_h2[(size_t)NPAIR * HH];          // 32 MB
__device__ __half d_xh[(size_t)BT * DD];             // 8 MB (fp16 x)
__device__ __half d_w1h[(size_t)EE * DD * HH];       // 32 MB  [E][D][H] (K x N row-major)
__device__ __half d_w2h[(size_t)EE * HH * HH];       // 64 MB
__device__ __half d_w3h[(size_t)EE * HH * OO];       // 32 MB
__device__ float  d_y[(size_t)NPAIR * OO];           // 32 MB gated partial outputs by position
__device__ int   d_pair_token[NPAIR];
__device__ float d_pair_gate[NPAIR];
__device__ int   d_pair_pos[NPAIR];                  // pair j -> position
__device__ int   d_counts[EE];
__device__ int   d_offsets[EE];
__device__ int   d_cursor[EE];
__device__ float d_sum_probs[EE];
__device__ float d_sum_gates[EE];
__device__ int   d_top_idx[NPAIR];
__device__ float d_top_g[NPAIR];

#define N1 ((size_t)EE * DD * HH)   // 16,777,216
#define N2 ((size_t)EE * HH * HH)   // 33,554,432
#define N3 ((size_t)EE * HH * OO)   // 16,777,216

// ---- shared fp32->fp16 convert of 8 contiguous elements ----
__device__ __forceinline__ void conv8(const float* __restrict__ src,
                                      __half* __restrict__ dst, size_t off) {
    float4 f0 = *(const float4*)(src + off);
    float4 f1 = *(const float4*)(src + off + 4);
    __half2 h[4];
    h[0] = __floats2half2_rn(f0.x, f0.y);
    h[1] = __floats2half2_rn(f0.z, f0.w);
    h[2] = __floats2half2_rn(f1.x, f1.y);
    h[3] = __floats2half2_rn(f1.z, f1.w);
    *(uint4*)(dst + off) = *(uint4*)h;
}

// ================= fat pre: W1 convert + gating (emits fp16 x) ==============
#define NCONV1B 8192u    // N1 / (256*8)
__global__ __launch_bounds__(256)
void fatpre_kernel(const float* __restrict__ W1,
                   const float* __restrict__ x,
                   const float* __restrict__ Wg,
                   const float* __restrict__ bg) {
    if (blockIdx.x < NCONV1B) {
        size_t i8 = ((size_t)blockIdx.x * 256 + threadIdx.x) * 8;
        conv8(W1, d_w1h, i8);
        return;
    }
    int t = blockIdx.x - NCONV1B;
    int tid = threadIdx.x;
    float acc[EE];
#pragma unroll
    for (int e = 0; e < EE; e++) acc[e] = 0.0f;
    const float* xr = x + (size_t)t * DD;
    __half* xh = d_xh + (size_t)t * DD;
    for (int d = tid; d < DD; d += 256) {
        float xv = xr[d];
        xh[d] = __float2half(xv);
        const float* w = Wg + (size_t)d * EE;
#pragma unroll
        for (int e = 0; e < EE; e++) acc[e] += xv * w[e];
    }
#pragma unroll
    for (int e = 0; e < EE; e++) {
#pragma unroll
        for (int off = 16; off > 0; off >>= 1)
            acc[e] += __shfl_down_sync(0xffffffffu, acc[e], off);
    }
    __shared__ float sred[8][EE];
    int warp = tid >> 5, lane = tid & 31;
    if (lane == 0) {
#pragma unroll
        for (int e = 0; e < EE; e++) sred[warp][e] = acc[e];
    }
    __syncthreads();
    if (tid == 0) {
        float logit[EE];
#pragma unroll
        for (int e = 0; e < EE; e++) {
            float s = sred[0][e];
#pragma unroll
            for (int w = 1; w < 8; w++) s += sred[w][e];
            logit[e] = s + bg[e];
        }
        float m = logit[0];
#pragma unroll
        for (int e = 1; e < EE; e++) m = fmaxf(m, logit[e]);
        float p[EE], se = 0.0f;
#pragma unroll
        for (int e = 0; e < EE; e++) { p[e] = __expf(logit[e] - m); se += p[e]; }
        float inv = 1.0f / se;
#pragma unroll
        for (int e = 0; e < EE; e++) atomicAdd(&d_sum_probs[e], p[e] * inv);
        int i0 = 0;
#pragma unroll
        for (int e = 1; e < EE; e++) if (logit[e] > logit[i0]) i0 = e;
        int i1 = (i0 == 0) ? 1 : 0;
#pragma unroll
        for (int e = 0; e < EE; e++)
            if (e != i0 && logit[e] > logit[i1]) i1 = e;
        float l0 = logit[i0], l1 = logit[i1];
        float mm = fmaxf(l0, l1);
        float e0 = __expf(l0 - mm), e1 = __expf(l1 - mm);
        float s2 = e0 + e1;
        float g0 = e0 / s2, g1 = e1 / s2;
        atomicAdd(&d_sum_gates[i0], g0);
        atomicAdd(&d_sum_gates[i1], g1);
        atomicAdd(&d_counts[i0], 1);
        atomicAdd(&d_counts[i1], 1);
        d_top_idx[t * 2 + 0] = i0;  d_top_g[t * 2 + 0] = g0;
        d_top_idx[t * 2 + 1] = i1;  d_top_g[t * 2 + 1] = g1;
    }
}

// tiny init for accumulators (before gating)
__global__ void init_acc_kernel() {
    if (threadIdx.x < EE) {
        d_counts[threadIdx.x] = 0;
        d_sum_probs[threadIdx.x] = 0.0f;
        d_sum_gates[threadIdx.x] = 0.0f;
    }
}

// ================= finalize: offsets + aux stats + tail-zero =================
__global__ void finalize_kernel(float* __restrict__ out, int out_size) {
    if (threadIdx.x == 0 && blockIdx.x == 0) {
        int off = 0;
        for (int e = 0; e < EE; e++) {
            d_offsets[e] = off;
            off += d_counts[e];
            d_cursor[e] = 0;
        }
        for (int i = OUT_TENSOR; i < out_size; i++) out[i] = 0.0f;  // tail is tiny
        float lb = 0.0f, ent = 0.0f;
        const float invT = 1.0f / (float)BT;
        for (int e = 0; e < EE; e++) {
            float ap = d_sum_probs[e] * invT;
            float ac = d_sum_gates[e] * invT;
            lb += ap * ac;
            ent -= ap * logf(ap + 1e-8f);
            out[OUT_TENSOR + 1 + e] = ac;
        }
        out[OUT_TENSOR] = 0.01f * (float)EE * lb;
        out[OUT_TENSOR + 1 + EE] = ent;
    }
}

// ================= scatter =================
__global__ void scatter_kernel() {
    int j = blockIdx.x * blockDim.x + threadIdx.x;
    if (j >= NPAIR) return;
    int t = j >> 1;
    int e = d_top_idx[j];
    int pos = d_offsets[e] + atomicAdd(&d_cursor[e], 1);
    d_pair_token[pos] = t;
    d_pair_gate[pos]  = d_top_g[j];
    d_pair_pos[j] = pos;
}

// ================= fp16 mma.sync expert GEMM (ldmatrix + 3-stage cp.async) ========
// CTA 128(M)x128(N), KC=64. warp grid 2m x 4n; warp tile 64x32; mma m16n8k16 f32-acc.
// Piggyback conversion rides in EXTRA x-columns (blockIdx.x >= NXG) so conv CTAs
// interleave with gemm CTAs in dispatch order (DRAM pipe overlaps tensor pipe).
#define KC 64
#define STAGE_BYTES 32768            // A 16KB + B 16KB
#define HDR_BYTES 1024
#define NSTAGE 3
#define SMEM_DYN (HDR_BYTES + NSTAGE*STAGE_BYTES)

template<int LAYER, int NCONVX>
__global__ __launch_bounds__(256, 2)
void expert_gemm_mma(const __half* __restrict__ Wh,
                     const float* __restrict__ bias,
                     const float* __restrict__ convsrc,
                     __half* __restrict__ convdst,
                     size_t convN) {
    constexpr int Kd = (LAYER == 1) ? DD : HH;
    constexpr int Nd = (LAYER == 3) ? OO : HH;
    constexpr int NCH = Kd / KC;   // 16 or 32
    constexpr int NXG = Nd / 128;  // gemm columns in x

    if (NCONVX > 0 && blockIdx.x >= (unsigned)NXG) {
        // -------- piggyback weight conversion (interleaved in dispatch order) -----
        // nconvb = NCONVX * gridDim.y * gridDim.z blocks; contiguous range per block.
        size_t nconvb = (size_t)NCONVX * gridDim.y * gridDim.z;
        size_t cb = ((size_t)blockIdx.z * gridDim.y + blockIdx.y) * NCONVX
                    + (blockIdx.x - NXG);
        size_t perblk = convN / nconvb;            // elements per block (pow2)
        size_t base = cb * perblk + (size_t)threadIdx.x * 8;
        for (size_t o = 0; o < perblk; o += 2048)  // 256 thr * 8 elems
            conv8(convsrc, convdst, base + o);
        return;
    }

    const int e   = blockIdx.z;
    const int cnt = d_counts[e];
    const int mtile = blockIdx.y;
    if (mtile * 128 >= cnt) return;
    const int base = d_offsets[e];
    const int nblk = blockIdx.x;

    extern __shared__ char smem_raw[];
    const uint32_t sb = smem_to_u32(smem_raw);
    int* stok    = (int*)smem_raw;            // [128]
    float* sgate = (float*)(smem_raw + 512);  // [128]

    const int tid = threadIdx.x;
    const int wid = tid >> 5;
    const int lid = tid & 31;
    const int g   = lid >> 2;     // 0..7
    const int tg  = lid & 3;      // 0..3
    const int m0  = (wid & 1) * 64;
    const int n0  = (wid >> 1) * 32;

    if (tid < 128) {
        int gr = mtile * 128 + tid;
        int idx = base + min(gr, cnt - 1);
        stok[tid]  = d_pair_token[idx];
        sgate[tid] = d_pair_gate[idx];
    }
    __syncthreads();

    // ---- cp.async mappings ----
    const int lsubA = tid & 7, lrowA = tid >> 3;     // A: 128 rows x 128B
    const int lsubB = tid & 15, lrowB = tid >> 4;    // B: 64 rows x 256B

    const __half* WhE = Wh + (size_t)e * Kd * Nd + (size_t)(nblk * 128);
    const __half* hsrc = (LAYER == 2) ? d_h1 : d_h2;

    uint32_t dstoffA[4], dstoffB[4];
    const char* asrc[4];
    const char* bsrc[4];
#pragma unroll
    for (int i = 0; i < 4; i++) {
        int rA = lrowA + 32 * i;
        dstoffA[i] = (uint32_t)(rA * 128 + ((lsubA ^ (rA & 7)) << 4));
        if (LAYER == 1) {
            asrc[i] = (const char*)(d_xh + (size_t)stok[rA] * DD) + lsubA * 16;
        } else {
            int gr = min(mtile * 128 + rA, cnt - 1);
            asrc[i] = (const char*)(hsrc + (size_t)(base + gr) * Kd) + lsubA * 16;
        }
        int rB = lrowB + 16 * i;
        dstoffB[i] = (uint32_t)(rB * 256 + ((lsubB ^ (rB & 7)) << 4));
        bsrc[i] = (const char*)(WhE + (size_t)rB * Nd) + lsubB * 16;
    }
    const size_t bstep = (size_t)KC * Nd * sizeof(__half);  // per-stage B advance

    // ---- ldmatrix lane constants ----
    const int til = lid >> 3, rin = lid & 7;
    const int thi = til >> 1, tlo = til & 1;
    uint32_t rowbaseA[4];
#pragma unroll
    for (int mt = 0; mt < 4; mt++)
        rowbaseA[mt] = (uint32_t)((m0 + mt * 16 + rin + tlo * 8) * 128);
    uint32_t koffA[4];
#pragma unroll
    for (int ks = 0; ks < 4; ks++)
        koffA[ks] = (uint32_t)((((ks * 2) + thi) ^ rin) << 4);
    const int klane = rin + tlo * 8;   // 0..15
    uint32_t lbB[2];
#pragma unroll
    for (int pr = 0; pr < 2; pr++) {
        int nc = (n0 >> 3) + pr * 2 + thi;
        lbB[pr] = (uint32_t)(klane * 256 + ((nc ^ (klane & 7)) << 4));
    }

    float acc[4][4][4];
#pragma unroll
    for (int mt = 0; mt < 4; mt++)
#pragma unroll
        for (int nt = 0; nt < 4; nt++)
#pragma unroll
            for (int c = 0; c < 4; c++) acc[mt][nt][c] = 0.0f;

    auto issue = [&](int s) {
        uint32_t sa = sb + HDR_BYTES + (s % NSTAGE) * STAGE_BYTES;
        uint32_t sB = sa + 16384;
        size_t aoff = (size_t)s * 128;       // 64 halves = 128 bytes along K
        size_t boff = (size_t)s * bstep;
#pragma unroll
        for (int i = 0; i < 4; i++) CP_ASYNC16(sa + dstoffA[i], asrc[i] + aoff);
#pragma unroll
        for (int i = 0; i < 4; i++) CP_ASYNC16_CG(sB + dstoffB[i], bsrc[i] + boff);
    };

    issue(0); CP_COMMIT();
    issue(1); CP_COMMIT();

    for (int c = 0; c < NCH; c++) {
        if (c + 1 < NCH) { CP_WAIT1(); } else { CP_WAIT0(); }
        __syncthreads();
        if (c + 2 < NCH) { issue(c + 2); CP_COMMIT(); }

        uint32_t sa = sb + HDR_BYTES + (c % NSTAGE) * STAGE_BYTES;
        uint32_t sB = sa + 16384;
#pragma unroll
        for (int ks = 0; ks < 4; ks++) {
            uint32_t b[8];
            ldsm_x4_t(b[0], b[1], b[2], b[3], sB + lbB[0] + ks * 4096);
            ldsm_x4_t(b[4], b[5], b[6], b[7], sB + lbB[1] + ks * 4096);
#pragma unroll
            for (int mt = 0; mt < 4; mt++) {
                uint32_t a0, a1, a2, a3;
                ldsm_x4(a0, a1, a2, a3, sa + rowbaseA[mt] + koffA[ks]);
                mma_f16(acc[mt][0][0], acc[mt][0][1], acc[mt][0][2], acc[mt][0][3],
                        a0, a1, a2, a3, b[0], b[1]);
                mma_f16(acc[mt][1][0], acc[mt][1][1], acc[mt][1][2], acc[mt][1][3],
                        a0, a1, a2, a3, b[2], b[3]);
                mma_f16(acc[mt][2][0], acc[mt][2][1], acc[mt][2][2], acc[mt][2][3],
                        a0, a1, a2, a3, b[4], b[5]);
                mma_f16(acc[mt][3][0], acc[mt][3][1], acc[mt][3][2], acc[mt][3][3],
                        a0, a1, a2, a3, b[6], b[7]);
            }
        }
    }

    // ---- epilogue ----
    const float* biasE = bias + (size_t)e * Nd + nblk * 128;
    __half* hdst = (LAYER == 1) ? d_h1 : d_h2;

#pragma unroll
    for (int mt = 0; mt < 4; mt++) {
#pragma unroll
        for (int nt = 0; nt < 4; nt++) {
            int col = n0 + nt * 8 + tg * 2;
            float bv0 = biasE[col], bv1 = biasE[col + 1];
#pragma unroll
            for (int half = 0; half < 2; half++) {
                int lr = m0 + mt * 16 + g + half * 8;
                int grow = mtile * 128 + lr;
                if (grow >= cnt) continue;
                float v0 = acc[mt][nt][half * 2 + 0] + bv0;
                float v1 = acc[mt][nt][half * 2 + 1] + bv1;
                if (LAYER != 3) {
                    __half2 v = __floats2half2_rn(fmaxf(v0, 0.0f), fmaxf(v1, 0.0f));
                    *(__half2*)(hdst + (size_t)(base + grow) * HH + nblk * 128 + col) = v;
                } else {
                    float gt = sgate[lr];
                    float2 v = make_float2(gt * v0, gt * v1);
                    *(float2*)(d_y + (size_t)(base + grow) * OO + nblk * 128 + col) = v;
                }
            }
        }
    }
}

// ================= combine: out[t] = y[pos(2t)] + y[pos(2t+1)] =================
__global__ void combine_kernel(float* __restrict__ out) {
    int t = blockIdx.x;
    int p0 = d_pair_pos[2 * t];
    int p1 = d_pair_pos[2 * t + 1];
    const float4* y0 = (const float4*)(d_y + (size_t)p0 * OO);
    const float4* y1 = (const float4*)(d_y + (size_t)p1 * OO);
    float4* dst = (float4*)(out + (size_t)t * OO);
    int i = threadIdx.x;             // 256 threads, 256 float4 per row
    float4 a = y0[i], b = y1[i];
    dst[i] = make_float4(a.x + b.x, a.y + b.y, a.z + b.z, a.w + b.w);
}

// ================= launch =================
extern "C" void kernel_launch(void* const* d_in, const int* in_sizes, int n_in,
                              void* d_out, int out_size) {
    const float* x  = (const float*)d_in[0];
    const float* Wg = (const float*)d_in[1];
    const float* bg = (const float*)d_in[2];
    const float* W1 = (const float*)d_in[3];
    const float* b1 = (const float*)d_in[4];
    const float* W2 = (const float*)d_in[5];
    const float* b2 = (const float*)d_in[6];
    const float* W3 = (const float*)d_in[7];
    const float* b3 = (const float*)d_in[8];
    float* out = (float*)d_out;

    cudaFuncSetAttribute((const void*)expert_gemm_mma<1, 8>, cudaFuncAttributeMaxDynamicSharedMemorySize, SMEM_DYN);
    cudaFuncSetAttribute((const void*)expert_gemm_mma<2, 8>, cudaFuncAttributeMaxDynamicSharedMemorySize, SMEM_DYN);
    cudaFuncSetAttribute((const void*)expert_gemm_mma<3, 0>, cudaFuncAttributeMaxDynamicSharedMemorySize, SMEM_DYN);

    __half* w1h = nullptr; cudaGetSymbolAddress((void**)&w1h, d_w1h);
    __half* w2h = nullptr; cudaGetSymbolAddress((void**)&w2h, d_w2h);
    __half* w3h = nullptr; cudaGetSymbolAddress((void**)&w3h, d_w3h);

    // gemm1 grid (16+8, 32, 8): x>=16 -> convert W2 (2048 blocks, 16384 elem each)
    // gemm2 grid (16+8, 32, 8): x>=16 -> convert W3 (2048 blocks, 8192 elem each)
    init_acc_kernel<<<1, 32>>>();                                            // 1
    fatpre_kernel<<<NCONV1B + BT, 256>>>(W1, x, Wg, bg);                     // 2 (W1 conv + gating)
    finalize_kernel<<<1, 32>>>(out, out_size);                               // 3
    scatter_kernel<<<NPAIR / 256, 256>>>();                                  // 4
    expert_gemm_mma<1, 8><<<dim3(24, 32, EE), 256, SMEM_DYN>>>(w1h, b1, W2, w2h, N2); // 5
    expert_gemm_mma<2, 8><<<dim3(24, 32, EE), 256, SMEM_DYN>>>(w2h, b2, W3, w3h, N3); // 6
    expert_gemm_mma<3, 0><<<dim3(8, 32, EE), 256, SMEM_DYN>>>(w3h, b3, nullptr, nullptr, 0); // 7
    combine_kernel<<<BT, 256>>>(out);                                        // 8
}